// round 15
// baseline (speedup 1.0000x reference)
#include <cuda_runtime.h>
#include <cuda_bf16.h>

// SoftPool2d: x (16, 96, 256, 256) f32, 2x2 window, stride 2, no pad.
// out (16, 96, 128, 128) f32.
//
// FINAL (R14 = R13 champion). Pure streaming kernel, provably at the HBM
// wall: 503.3MB compulsory traffic at ~6.81 TB/s device counter (86% of
// spec, canonical for a 4:1 read/write mix) = ~70us kernel / ~74us e2e.
// Three distinct geometries (MLP4/full-occ, MLP8/half-occ, warp-dense MLP4)
// all converge to the same DRAM% with RF exactly full (32 regs x 2048 thr);
// every non-DRAM subsystem has >=50% slack.
//
// Geometry: one warp per (plane, output row). Thread i loads r0[i], r0[i+32],
// r1[i], r1[i+32] -> every LDG.128 is fully dense (512B contiguous per warp,
// all sectors used once). 4 front-batched streaming loads (MLP_p1=4), stable
// softmax via __expf, two dense float2 streaming stores.

#define H 256
#define W 256
#define HO 128
#define WO 128

#define BC 1536           // B*C planes
#define NWARP (BC * 128)  // one warp per (plane, output row)

__device__ __forceinline__ float softpool4(float t0, float t1, float t2, float t3) {
    float m = fmaxf(fmaxf(t0, t1), fmaxf(t2, t3));
    float e0 = __expf(t0 - m);
    float e1 = __expf(t1 - m);
    float e2 = __expf(t2 - m);
    float e3 = __expf(t3 - m);
    float num = fmaf(t0, e0, fmaf(t1, e1, fmaf(t2, e2, t3 * e3)));
    float den = e0 + e1 + e2 + e3;
    return num * __fdividef(1.0f, den);
}

__global__ __launch_bounds__(256, 8) void SoftPool2d_850403524762_kernel(
    const float* __restrict__ x, float* __restrict__ out) {
    int lane = threadIdx.x & 31;
    int gw = blockIdx.x * 8 + (threadIdx.x >> 5);  // global warp id

    int ho = gw & 127;   // output row
    int bc = gw >> 7;    // fused batch*channel plane

    // input rows 2*ho and 2*ho+1 of plane bc (each row = 64 float4)
    const float4* r0 = (const float4*)(x + (size_t)bc * (H * W) + (size_t)(2 * ho) * W);
    const float4* r1 = r0 + (W / 4);

    // 4 independent, fully-dense streaming loads (warp covers 512B per LDG)
    float4 a0 = __ldcs(r0 + lane);
    float4 a1 = __ldcs(r0 + lane + 32);
    float4 b0 = __ldcs(r1 + lane);
    float4 b1 = __ldcs(r1 + lane + 32);

    // a0/b0 cover input cols [4*lane, 4*lane+4) -> output cols 2*lane, 2*lane+1
    // a1/b1 cover input cols 128 + [4*lane, ...) -> output cols 64 + 2*lane, +1
    float2 o0, o1;
    o0.x = softpool4(a0.x, a0.y, b0.x, b0.y);
    o0.y = softpool4(a0.z, a0.w, b0.z, b0.w);
    o1.x = softpool4(a1.x, a1.y, b1.x, b1.y);
    o1.y = softpool4(a1.z, a1.w, b1.z, b1.w);

    float2* orow = (float2*)(out + (size_t)bc * (HO * WO) + (size_t)ho * WO);
    __stcs(orow + lane, o0);
    __stcs(orow + lane + 32, o1);
}

extern "C" void kernel_launch(void* const* d_in, const int* in_sizes, int n_in,
                              void* d_out, int out_size) {
    const float* x = (const float*)d_in[0];
    float* out = (float*)d_out;
    const int threads = 256;                 // 8 warps/block
    const int blocks = NWARP / 8;            // 24576
    SoftPool2d_850403524762_kernel<<<blocks, threads>>>(x, out);
}

// round 16
// speedup vs baseline: 1.0022x; 1.0022x over previous
#include <cuda_runtime.h>
#include <cuda_bf16.h>

// SoftPool2d: x (16, 96, 256, 256) f32, 2x2 window, stride 2, no pad.
// out (16, 96, 128, 128) f32.
//
// R15: champion geometry (warp-dense MLP4, 32 regs, 2048 thr/SM) with
// 512-thread blocks instead of 256 -> 12288 blocks, half the CTA-wave
// transitions / scheduling events. Per-warp work identical to R13/R14.
// HBM-wall kernel: 503.3MB compulsory traffic @ ~6.88 TB/s (86-87% DRAM),
// L1tex wavefront queue saturated (64 warps x 4 LDG ~ 256 > ~248 queue cap),
// so MLP/occupancy axis is exhausted; this tests the last knob (wave quant).

#define H 256
#define W 256
#define HO 128
#define WO 128

#define BC 1536           // B*C planes
#define NWARP (BC * 128)  // one warp per (plane, output row)

__device__ __forceinline__ float softpool4(float t0, float t1, float t2, float t3) {
    float m = fmaxf(fmaxf(t0, t1), fmaxf(t2, t3));
    float e0 = __expf(t0 - m);
    float e1 = __expf(t1 - m);
    float e2 = __expf(t2 - m);
    float e3 = __expf(t3 - m);
    float num = fmaf(t0, e0, fmaf(t1, e1, fmaf(t2, e2, t3 * e3)));
    float den = e0 + e1 + e2 + e3;
    return num * __fdividef(1.0f, den);
}

__global__ __launch_bounds__(512, 4) void SoftPool2d_850403524762_kernel(
    const float* __restrict__ x, float* __restrict__ out) {
    int lane = threadIdx.x & 31;
    int gw = blockIdx.x * 16 + (threadIdx.x >> 5);  // global warp id

    int ho = gw & 127;   // output row
    int bc = gw >> 7;    // fused batch*channel plane

    // input rows 2*ho and 2*ho+1 of plane bc (each row = 64 float4)
    const float4* r0 = (const float4*)(x + (size_t)bc * (H * W) + (size_t)(2 * ho) * W);
    const float4* r1 = r0 + (W / 4);

    // 4 independent, fully-dense streaming loads (warp covers 512B per LDG)
    float4 a0 = __ldcs(r0 + lane);
    float4 a1 = __ldcs(r0 + lane + 32);
    float4 b0 = __ldcs(r1 + lane);
    float4 b1 = __ldcs(r1 + lane + 32);

    // a0/b0 cover input cols [4*lane, 4*lane+4) -> output cols 2*lane, 2*lane+1
    // a1/b1 cover input cols 128 + [4*lane, ...) -> output cols 64 + 2*lane, +1
    float2 o0, o1;
    o0.x = softpool4(a0.x, a0.y, b0.x, b0.y);
    o0.y = softpool4(a0.z, a0.w, b0.z, b0.w);
    o1.x = softpool4(a1.x, a1.y, b1.x, b1.y);
    o1.y = softpool4(a1.z, a1.w, b1.z, b1.w);

    float2* orow = (float2*)(out + (size_t)bc * (HO * WO) + (size_t)ho * WO);
    __stcs(orow + lane, o0);
    __stcs(orow + lane + 32, o1);
}

extern "C" void kernel_launch(void* const* d_in, const int* in_sizes, int n_in,
                              void* d_out, int out_size) {
    const float* x = (const float*)d_in[0];
    float* out = (float*)d_out;
    const int threads = 512;                 // 16 warps/block
    const int blocks = NWARP / 16;           // 12288
    SoftPool2d_850403524762_kernel<<<blocks, threads>>>(x, out);
}

// round 17
// speedup vs baseline: 1.0043x; 1.0022x over previous
#include <cuda_runtime.h>
#include <cuda_bf16.h>

// SoftPool2d: x (16, 96, 256, 256) f32, 2x2 window, stride 2, no pad.
// out (16, 96, 128, 128) f32.
//
// FINAL. Pure streaming kernel at the HBM wall: 503.3MB compulsory traffic
// @ 6.82-6.88 TB/s (86% of 8TB/s spec — canonical ceiling for a 4:1
// read:write mix). Four geometries converged to the same 73.8-74.2us /
// 86% DRAM plateau; in-flight-loads/SM is RF-bound (32 regs x 2048 thr =
// full 64K RF) and L1tex-queue-bound (~256 issued ~ 248 queue cap). All
// non-DRAM subsystems have >=50% slack. No further kernel-side lever exists.
//
// Geometry: one warp per (plane, output row); 512-thread blocks (16 warps,
// 4 CTAs/SM). Thread i loads r0[lane], r0[lane+32], r1[lane], r1[lane+32]:
// every LDG.128 fully dense (512B contiguous/warp, each sector used once),
// 4 front-batched streaming loads (MLP_p1=4). Stable softmax via __expf
// (rel_err 8e-8). Two dense float2 streaming stores.

#define H 256
#define W 256
#define HO 128
#define WO 128

#define BC 1536           // B*C planes
#define NWARP (BC * 128)  // one warp per (plane, output row)

__device__ __forceinline__ float softpool4(float t0, float t1, float t2, float t3) {
    float m = fmaxf(fmaxf(t0, t1), fmaxf(t2, t3));
    float e0 = __expf(t0 - m);
    float e1 = __expf(t1 - m);
    float e2 = __expf(t2 - m);
    float e3 = __expf(t3 - m);
    float num = fmaf(t0, e0, fmaf(t1, e1, fmaf(t2, e2, t3 * e3)));
    float den = e0 + e1 + e2 + e3;
    return num * __fdividef(1.0f, den);
}

__global__ __launch_bounds__(512, 4) void SoftPool2d_850403524762_kernel(
    const float* __restrict__ x, float* __restrict__ out) {
    int lane = threadIdx.x & 31;
    int gw = blockIdx.x * 16 + (threadIdx.x >> 5);  // global warp id

    int ho = gw & 127;   // output row
    int bc = gw >> 7;    // fused batch*channel plane

    // input rows 2*ho and 2*ho+1 of plane bc (each row = 64 float4)
    const float4* r0 = (const float4*)(x + (size_t)bc * (H * W) + (size_t)(2 * ho) * W);
    const float4* r1 = r0 + (W / 4);

    // 4 independent, fully-dense streaming loads (warp covers 512B per LDG)
    float4 a0 = __ldcs(r0 + lane);
    float4 a1 = __ldcs(r0 + lane + 32);
    float4 b0 = __ldcs(r1 + lane);
    float4 b1 = __ldcs(r1 + lane + 32);

    // a0/b0 cover input cols [4*lane, 4*lane+4) -> output cols 2*lane, 2*lane+1
    // a1/b1 cover input cols 128 + [4*lane, ...) -> output cols 64 + 2*lane, +1
    float2 o0, o1;
    o0.x = softpool4(a0.x, a0.y, b0.x, b0.y);
    o0.y = softpool4(a0.z, a0.w, b0.z, b0.w);
    o1.x = softpool4(a1.x, a1.y, b1.x, b1.y);
    o1.y = softpool4(a1.z, a1.w, b1.z, b1.w);

    float2* orow = (float2*)(out + (size_t)bc * (HO * WO) + (size_t)ho * WO);
    __stcs(orow + lane, o0);
    __stcs(orow + lane + 32, o1);
}

extern "C" void kernel_launch(void* const* d_in, const int* in_sizes, int n_in,
                              void* d_out, int out_size) {
    const float* x = (const float*)d_in[0];
    float* out = (float*)d_out;
    const int threads = 512;                 // 16 warps/block
    const int blocks = NWARP / 16;           // 12288
    SoftPool2d_850403524762_kernel<<<blocks, threads>>>(x, out);
}